// round 1
// baseline (speedup 1.0000x reference)
#include <cuda_runtime.h>
#include <cstddef>

#define N_NODES_MAX 100000
#define DF 128

// Scratch: __device__ globals (no cudaMalloc allowed anywhere).
__device__ float g_agg[(size_t)N_NODES_MAX * DF];
__device__ float g_hid[(size_t)N_NODES_MAX * DF];

// ---------------------------------------------------------------------------
// agg = X   (vectorized copy)
// ---------------------------------------------------------------------------
__global__ void copy_init_kernel(const float4* __restrict__ src,
                                 float4* __restrict__ dst, int n4) {
    int i = blockIdx.x * blockDim.x + threadIdx.x;
    if (i < n4) dst[i] = src[i];
}

// ---------------------------------------------------------------------------
// For each edge e: agg[ra[e]] += X[rb[e]];  agg[rb[e]] += X[ra[e]]
// One warp per edge, each lane handles one float4 (32 lanes * 4 = 128 feats).
// Uses red.global.add.v4.f32 (sm_90+) -> 16B no-return L2 reductions.
// ---------------------------------------------------------------------------
__global__ void edge_scatter_kernel(const float* __restrict__ X,
                                    const int* __restrict__ ra,
                                    const int* __restrict__ rb,
                                    float* __restrict__ agg, int nE) {
    int e = blockIdx.x * (blockDim.x >> 5) + (threadIdx.x >> 5);
    if (e >= nE) return;
    int lane = threadIdx.x & 31;
    int a = ra[e];
    int b = rb[e];
    const float4 xb = *reinterpret_cast<const float4*>(X + (size_t)b * DF + lane * 4);
    const float4 xa = *reinterpret_cast<const float4*>(X + (size_t)a * DF + lane * 4);
    float* pa = agg + (size_t)a * DF + lane * 4;
    float* pb = agg + (size_t)b * DF + lane * 4;
    asm volatile("red.global.add.v4.f32 [%0], {%1, %2, %3, %4};"
                 :: "l"(pa), "f"(xb.x), "f"(xb.y), "f"(xb.z), "f"(xb.w)
                 : "memory");
    asm volatile("red.global.add.v4.f32 [%0], {%1, %2, %3, %4};"
                 :: "l"(pb), "f"(xa.x), "f"(xa.y), "f"(xa.z), "f"(xa.w)
                 : "memory");
}

// ---------------------------------------------------------------------------
// C[M,128] = act(A[M,128] @ W[128,128] + bias)
// Block: 256 threads, 64-row tile. Each thread computes a 4x8 micro-tile.
// W (64KB) + A-tile (64x132 padded, 33KB) live in dynamic smem (~97KB).
// ---------------------------------------------------------------------------
template <bool RELU>
__global__ void __launch_bounds__(256, 2)
gemm128_kernel(const float* __restrict__ A, const float* __restrict__ W,
               const float* __restrict__ bias, float* __restrict__ C, int M) {
    extern __shared__ float sm[];
    float* Ws = sm;               // [128][128]
    float* As = sm + 128 * 128;   // [64][132]  (pad 4 to break bank conflicts)

    const int tx = threadIdx.x;
    const int row0 = blockIdx.x * 64;

    // Load W: 16384 floats = 4096 float4 / 256 threads = 16 each.
    {
        const float4* Wg = reinterpret_cast<const float4*>(W);
        float4* Wsv = reinterpret_cast<float4*>(Ws);
#pragma unroll
        for (int i = 0; i < 16; i++) Wsv[tx + i * 256] = Wg[tx + i * 256];
    }
    // Load A tile: 64 rows x 128 cols = 2048 float4 / 256 threads = 8 each.
    {
#pragma unroll
        for (int i = 0; i < 8; i++) {
            int idx4 = tx + i * 256;      // 0..2047
            int r = idx4 >> 5;            // row within tile
            int c4 = idx4 & 31;           // float4 index within row
            float4 v = make_float4(0.f, 0.f, 0.f, 0.f);
            if (row0 + r < M)
                v = reinterpret_cast<const float4*>(A + (size_t)(row0 + r) * DF)[c4];
            *reinterpret_cast<float4*>(&As[r * 132 + c4 * 4]) = v;
        }
    }
    __syncthreads();

    const int tm = tx >> 4;   // 0..15 -> rows tm*4 .. tm*4+3
    const int tn = tx & 15;   // 0..15 -> cols tn*8 .. tn*8+7

    float acc[4][8];
#pragma unroll
    for (int i = 0; i < 4; i++)
#pragma unroll
        for (int j = 0; j < 8; j++) acc[i][j] = 0.f;

#pragma unroll 4
    for (int k = 0; k < 128; k++) {
        float a[4];
#pragma unroll
        for (int i = 0; i < 4; i++) a[i] = As[(tm * 4 + i) * 132 + k];
        float4 b0 = *reinterpret_cast<const float4*>(&Ws[k * 128 + tn * 8]);
        float4 b1 = *reinterpret_cast<const float4*>(&Ws[k * 128 + tn * 8 + 4]);
        float b[8] = {b0.x, b0.y, b0.z, b0.w, b1.x, b1.y, b1.z, b1.w};
#pragma unroll
        for (int i = 0; i < 4; i++)
#pragma unroll
            for (int j = 0; j < 8; j++)
                acc[i][j] = fmaf(a[i], b[j], acc[i][j]);
    }

    float bv[8];
#pragma unroll
    for (int j = 0; j < 8; j++) bv[j] = __ldg(&bias[tn * 8 + j]);

#pragma unroll
    for (int i = 0; i < 4; i++) {
        int r = row0 + tm * 4 + i;
        if (r < M) {
            float o[8];
#pragma unroll
            for (int j = 0; j < 8; j++) {
                float v = acc[i][j] + bv[j];
                o[j] = RELU ? fmaxf(v, 0.f) : v;
            }
            float* cp = C + (size_t)r * DF + tn * 8;
            *reinterpret_cast<float4*>(cp)     = make_float4(o[0], o[1], o[2], o[3]);
            *reinterpret_cast<float4*>(cp + 4) = make_float4(o[4], o[5], o[6], o[7]);
        }
    }
}

// ---------------------------------------------------------------------------
// Launch
// Inputs (metadata order): X, ref_a, ref_b, W_hidden, b_hidden, W_out, b_out
// ---------------------------------------------------------------------------
extern "C" void kernel_launch(void* const* d_in, const int* in_sizes, int n_in,
                              void* d_out, int out_size) {
    const float* X  = (const float*)d_in[0];
    const int*   ra = (const int*)  d_in[1];
    const int*   rb = (const int*)  d_in[2];
    const float* Wh = (const float*)d_in[3];
    const float* bh = (const float*)d_in[4];
    const float* Wo = (const float*)d_in[5];
    const float* bo = (const float*)d_in[6];
    float* out = (float*)d_out;

    const int M  = in_sizes[0] / DF;   // 100000 nodes
    const int nE = in_sizes[1];        // 600000 edges

    float *agg = nullptr, *hid = nullptr;
    cudaGetSymbolAddress((void**)&agg, g_agg);
    cudaGetSymbolAddress((void**)&hid, g_hid);

    const int smem_bytes = (128 * 128 + 64 * 132) * (int)sizeof(float);  // 99328
    cudaFuncSetAttribute(gemm128_kernel<true>,
                         cudaFuncAttributeMaxDynamicSharedMemorySize, smem_bytes);
    cudaFuncSetAttribute(gemm128_kernel<false>,
                         cudaFuncAttributeMaxDynamicSharedMemorySize, smem_bytes);

    // 1) agg = X
    {
        int n4 = M * DF / 4;
        int grid = (n4 + 255) / 256;
        copy_init_kernel<<<grid, 256>>>((const float4*)X, (float4*)agg, n4);
    }

    // 2) scatter-add both edge directions (1 warp per edge, 8 warps/block)
    {
        int warps_per_block = 8;
        int grid = (nE + warps_per_block - 1) / warps_per_block;
        edge_scatter_kernel<<<grid, warps_per_block * 32>>>(X, ra, rb, agg, nE);
    }

    // 3) hid = relu(agg @ Wh + bh)
    {
        int grid = (M + 63) / 64;
        gemm128_kernel<true><<<grid, 256, smem_bytes>>>(agg, Wh, bh, hid, M);
    }

    // 4) out = hid @ Wo + bo
    {
        int grid = (M + 63) / 64;
        gemm128_kernel<false><<<grid, 256, smem_bytes>>>(hid, Wo, bo, out, M);
    }
}

// round 14
// speedup vs baseline: 1.7550x; 1.7550x over previous
#include <cuda_runtime.h>
#include <cuda_bf16.h>
#include <cstdint>
#include <cstddef>

#define DF 128
#define N_NODES_MAX 100000

__device__ float g_agg[(size_t)N_NODES_MAX * DF];

// tcgen05 is arch-SPECIFIC (sm_103a): only emit it when the compile pass has
// the 'a' feature set. The plain compute_103/sm_103 pass gets an FFMA fallback.
#if defined(__CUDA_ARCH__) && (__CUDA_ARCH__ == 1030) && \
    (defined(__CUDA_ARCH_FEAT_SM103_ALL) || defined(__CUDA_ARCH_SPECIFIC__) || \
     defined(__CUDA_ARCH_FEAT_SM103A_ALL))
#define USE_TCGEN05 1
#else
#define USE_TCGEN05 0
#endif

// ---------------------------------------------------------------------------
// PTX helpers (safe on all targets)
// ---------------------------------------------------------------------------
__device__ __forceinline__ uint32_t smem_u32(const void* p) {
    uint32_t a;
    asm("{ .reg .u64 t; cvta.to.shared.u64 t, %1; cvt.u32.u64 %0, t; }" : "=r"(a) : "l"(p));
    return a;
}
__device__ __forceinline__ uint32_t elect_one() {
    uint32_t p;
    asm volatile("{ .reg .pred p; elect.sync _|p, 0xFFFFFFFF; selp.b32 %0,1,0,p; }" : "=r"(p));
    return p;
}
__device__ __forceinline__ uint32_t sw128(uint32_t off) { return off ^ ((off >> 3) & 0x70); }

static constexpr uint64_t DESC_BASE =
    (uint64_t(2) << 61) | (uint64_t(1) << 46) | (uint64_t(64) << 32) | (uint64_t(1) << 16);
__device__ __forceinline__ uint64_t make_desc(uint32_t addr) {
    return DESC_BASE | ((uint64_t)(addr >> 4) & 0x3FFF);
}

#define MBARRIER_INIT(addr, cnt) \
    asm volatile("mbarrier.init.shared.b64 [%0], %1;" :: "r"(addr), "r"(cnt) : "memory")

#define MBARRIER_WAIT_PARITY(mbar_smem_addr, phase_parity) do { \
    uint32_t _mbar = (uint32_t)(mbar_smem_addr); \
    uint32_t _parity = (uint32_t)(phase_parity); \
    uint32_t _done; \
    asm volatile( \
        "{\n\t" \
        ".reg .pred p;\n\t" \
        "mbarrier.try_wait.parity.acquire.cta.shared::cta.b64 p, [%1], %2;\n\t" \
        "selp.b32 %0, 1, 0, p;\n\t" \
        "}" \
        : "=r"(_done) : "r"(_mbar), "r"(_parity) : "memory"); \
    if (!_done) { \
        asm volatile( \
            "{\n\t" \
            ".reg .pred P1;\n\t" \
            "WAIT_LOOP_%=:\n\t" \
            "mbarrier.try_wait.parity.acquire.cta.shared::cta.b64 P1, [%0], %1, 0x989680;\n\t" \
            "@P1 bra.uni WAIT_DONE_%=;\n\t" \
            "bra.uni WAIT_LOOP_%=;\n\t" \
            "WAIT_DONE_%=:\n\t" \
            "}" \
            :: "r"(_mbar), "r"(_parity) : "memory"); \
    } \
} while(0)

#if USE_TCGEN05
#define LDTM_X32(r, tmem_addr) \
    asm volatile( \
        "tcgen05.ld.sync.aligned.32x32b.x32.b32 " \
        "{%0, %1, %2, %3, %4, %5, %6, %7, " \
        " %8, %9, %10, %11, %12, %13, %14, %15, " \
        " %16, %17, %18, %19, %20, %21, %22, %23, " \
        " %24, %25, %26, %27, %28, %29, %30, %31}, [%32];" \
        : "=r"((r)[0]),  "=r"((r)[1]),  "=r"((r)[2]),  "=r"((r)[3]), \
          "=r"((r)[4]),  "=r"((r)[5]),  "=r"((r)[6]),  "=r"((r)[7]), \
          "=r"((r)[8]),  "=r"((r)[9]),  "=r"((r)[10]), "=r"((r)[11]), \
          "=r"((r)[12]), "=r"((r)[13]), "=r"((r)[14]), "=r"((r)[15]), \
          "=r"((r)[16]), "=r"((r)[17]), "=r"((r)[18]), "=r"((r)[19]), \
          "=r"((r)[20]), "=r"((r)[21]), "=r"((r)[22]), "=r"((r)[23]), \
          "=r"((r)[24]), "=r"((r)[25]), "=r"((r)[26]), "=r"((r)[27]), \
          "=r"((r)[28]), "=r"((r)[29]), "=r"((r)[30]), "=r"((r)[31]) \
        : "r"(tmem_addr))

#define TM_WAIT_LD() asm volatile("tcgen05.wait::ld.sync.aligned;" ::: "memory")

// idesc: dtype=F32(1<<4), atype=BF16(1<<7), btype=BF16(1<<10), N=128((128/8)<<17), M=128((128/16)<<24)
#define MMA_IDESC 0x8200490u

__device__ __forceinline__ void mma_bf16_ss(uint32_t d, uint64_t a, uint64_t b, bool acc) {
    uint32_t e = acc ? 1u : 0u;
    asm volatile(
        "{ .reg .pred p; setp.ne.u32 p, %5, 0;\n\t"
        "tcgen05.mma.cta_group::1.kind::f16 [%0], %1, %2, %3, {%4,%4,%4,%4}, p; }"
        :: "r"(d), "l"(a), "l"(b), "r"(MMA_IDESC), "r"(0u), "r"(e) : "memory");
}
#endif  // USE_TCGEN05

// bf16 hi/lo split of two floats, packed as bf16x2 (element0 low half)
__device__ __forceinline__ void split2(float x0, float x1, uint32_t& hi, uint32_t& lo) {
    __nv_bfloat16 h0 = __float2bfloat16(x0), h1 = __float2bfloat16(x1);
    float f0 = __bfloat162float(h0), f1 = __bfloat162float(h1);
    __nv_bfloat16 l0 = __float2bfloat16(x0 - f0), l1 = __float2bfloat16(x1 - f1);
    hi = (uint32_t)__bfloat16_as_ushort(h0) | ((uint32_t)__bfloat16_as_ushort(h1) << 16);
    lo = (uint32_t)__bfloat16_as_ushort(l0) | ((uint32_t)__bfloat16_as_ushort(l1) << 16);
}

// ---------------------------------------------------------------------------
// smem layout (bytes) -- tcgen05 path. Each operand region = 2 K-chunks of
// [128 rows x 64 bf16] (16 KB per chunk, SW128-swizzled).
// ---------------------------------------------------------------------------
#define SM_TMEM   0
#define SM_MBAR   8
#define SM_A_HI   1024
#define SM_A_LO   (SM_A_HI + 32768)
#define SM_WH_HI  (SM_A_LO + 32768)
#define SM_WH_LO  (SM_WH_HI + 32768)
#define SM_WO_HI  (SM_WH_LO + 32768)
#define SM_WO_LO  (SM_WO_HI + 32768)
#define SM_BH     (SM_WO_LO + 32768)
#define SM_BO     (SM_BH + 512)
// ---- fallback (fp32) layout: 64-row tiles ----
#define SMF_AS    1024                      // As[64][132] f32  = 33792
#define SMF_HS    (SMF_AS + 33792)          // Hs[64][132] f32  = 33792
#define SMF_W1    (SMF_HS + 33792)          // Wh [128][128] f32 = 65536
#define SMF_W2    (SMF_W1 + 65536)          // Wo [128][128] f32 = 65536
#define SMF_BH    (SMF_W2 + 65536)
#define SMF_BO    (SMF_BH + 512)
#define SMF_END   (SMF_BO + 512)
#define SM_TOTAL  203776                    // max(both layouts), < 227KB cap

#if USE_TCGEN05
__device__ __forceinline__ void issue_gemm3x(uint32_t d_tmem, uint32_t sb,
                                             uint32_t aHiOff, uint32_t aLoOff,
                                             uint32_t bHiOff, uint32_t bLoOff,
                                             uint32_t mbar) {
    uint64_t aHi = make_desc(sb + aHiOff), aLo = make_desc(sb + aLoOff);
    uint64_t bHi = make_desc(sb + bHiOff), bLo = make_desc(sb + bLoOff);
    uint64_t aP[3] = {aHi, aHi, aLo};
    uint64_t bP[3] = {bHi, bLo, bHi};
    bool first = true;
#pragma unroll
    for (int p = 0; p < 3; p++) {
#pragma unroll
        for (int s = 0; s < 8; s++) {
            uint64_t off = (uint64_t)((s >> 2) * 1024 + (s & 3) * 2);
            mma_bf16_ss(d_tmem, aP[p] + off, bP[p] + off, !first);
            first = false;
        }
    }
    asm volatile("tcgen05.commit.cta_group::1.mbarrier::arrive::one.shared::cluster.b64 [%0];"
                 :: "r"(mbar) : "memory");
}
#endif

// ---------------------------------------------------------------------------
// Fused persistent MLP: out = (relu(A @ Wh + bh)) @ Wo + bo
// ---------------------------------------------------------------------------
__global__ void __launch_bounds__(128, 1)
fused_mlp_kernel(const float* __restrict__ A, const float* __restrict__ Wh,
                 const float* __restrict__ bh, const float* __restrict__ Wo,
                 const float* __restrict__ bo, float* __restrict__ out, int M) {
    extern __shared__ char smem[];
    const uint32_t sb = smem_u32(smem);
    const int tid = threadIdx.x, wid = tid >> 5, lid = tid & 31;

#if USE_TCGEN05
    if (wid == 0) {
        asm volatile("tcgen05.alloc.cta_group::1.sync.aligned.shared::cta.b32 [%0], %1;"
                     :: "r"(sb + SM_TMEM), "r"(256u) : "memory");
    }
    if (tid == 0) { MBARRIER_INIT(sb + SM_MBAR, 1u); }
    __syncthreads();
    uint32_t tmem;
    asm volatile("ld.shared.b32 %0, [%1];" : "=r"(tmem) : "r"(sb + SM_TMEM));
    const uint32_t D1 = tmem, D2 = tmem + 128;

    float* bhs = (float*)(smem + SM_BH);
    float* bos = (float*)(smem + SM_BO);
    bhs[tid] = bh[tid];
    bos[tid] = bo[tid];

    // ---- W^T hi/lo split into smem (once per persistent CTA) ----
    for (int kp = wid; kp < 64; kp += 4) {
        const int k0 = kp * 2;
        float4 r0 = *(const float4*)(Wh + (size_t)k0 * DF + lid * 4);
        float4 r1 = *(const float4*)(Wh + (size_t)(k0 + 1) * DF + lid * 4);
        float4 s0 = *(const float4*)(Wo + (size_t)k0 * DF + lid * 4);
        float4 s1 = *(const float4*)(Wo + (size_t)(k0 + 1) * DF + lid * 4);
        float h0[4] = {r0.x, r0.y, r0.z, r0.w};
        float h1[4] = {r1.x, r1.y, r1.z, r1.w};
        float o0[4] = {s0.x, s0.y, s0.z, s0.w};
        float o1[4] = {s1.x, s1.y, s1.z, s1.w};
        const int chunk = k0 >> 6;
        const int kin = (k0 & 63) * 2;
#pragma unroll
        for (int j = 0; j < 4; j++) {
            int n = lid * 4 + j;
            uint32_t swo = sw128((uint32_t)(n * 128 + kin)) + chunk * 16384;
            uint32_t hi, lo;
            split2(h0[j], h1[j], hi, lo);
            *(uint32_t*)(smem + SM_WH_HI + swo) = hi;
            *(uint32_t*)(smem + SM_WH_LO + swo) = lo;
            split2(o0[j], o1[j], hi, lo);
            *(uint32_t*)(smem + SM_WO_HI + swo) = hi;
            *(uint32_t*)(smem + SM_WO_LO + swo) = lo;
        }
    }
    asm volatile("fence.proxy.async.shared::cta;" ::: "memory");
    __syncthreads();

    const int nTiles = (M + 127) >> 7;
    int ph = 0;

    for (int t = blockIdx.x; t < nTiles; t += gridDim.x) {
        const int m0 = t << 7;

        for (int r = wid; r < 128; r += 4) {
            const int row = m0 + r;
            float4 v = make_float4(0.f, 0.f, 0.f, 0.f);
            if (row < M) v = *(const float4*)(A + (size_t)row * DF + lid * 4);
            uint32_t hi0, lo0, hi1, lo1;
            split2(v.x, v.y, hi0, lo0);
            split2(v.z, v.w, hi1, lo1);
            const int chunk = lid >> 4;
            uint32_t swo = sw128((uint32_t)(r * 128 + (lid & 15) * 8)) + chunk * 16384;
            *(uint2*)(smem + SM_A_HI + swo) = make_uint2(hi0, hi1);
            *(uint2*)(smem + SM_A_LO + swo) = make_uint2(lo0, lo1);
        }
        asm volatile("fence.proxy.async.shared::cta;" ::: "memory");
        __syncthreads();

        // ---- GEMM1 ----
        if (wid == 0) {
            asm volatile("tcgen05.fence::after_thread_sync;" ::: "memory");
            if (elect_one())
                issue_gemm3x(D1, sb, SM_A_HI, SM_A_LO, SM_WH_HI, SM_WH_LO, sb + SM_MBAR);
        }
        MBARRIER_WAIT_PARITY(sb + SM_MBAR, ph);
        ph ^= 1;
        asm volatile("tcgen05.fence::after_thread_sync;" ::: "memory");

        // ---- epi1: hid = relu(D1 + bh) -> A region (bf16 hi/lo) ----
        const int r = tid;
#pragma unroll
        for (int p = 0; p < 4; p++) {
            uint32_t dreg[32];
            LDTM_X32(dreg, D1 + p * 32);
            TM_WAIT_LD();
            const int chunk = p >> 1;
            const uint32_t base = (uint32_t)(r * 128 + (p & 1) * 64);
#pragma unroll
            for (int j = 0; j < 16; j++) {
                float x0 = __uint_as_float(dreg[2 * j]) + bhs[p * 32 + 2 * j];
                float x1 = __uint_as_float(dreg[2 * j + 1]) + bhs[p * 32 + 2 * j + 1];
                x0 = fmaxf(x0, 0.f);
                x1 = fmaxf(x1, 0.f);
                uint32_t hi, lo;
                split2(x0, x1, hi, lo);
                uint32_t swo = sw128(base + 4 * j) + chunk * 16384;
                *(uint32_t*)(smem + SM_A_HI + swo) = hi;
                *(uint32_t*)(smem + SM_A_LO + swo) = lo;
            }
        }
        asm volatile("tcgen05.fence::before_thread_sync;" ::: "memory");
        asm volatile("fence.proxy.async.shared::cta;" ::: "memory");
        __syncthreads();

        // ---- GEMM2 ----
        if (wid == 0) {
            asm volatile("tcgen05.fence::after_thread_sync;" ::: "memory");
            if (elect_one())
                issue_gemm3x(D2, sb, SM_A_HI, SM_A_LO, SM_WO_HI, SM_WO_LO, sb + SM_MBAR);
        }
        MBARRIER_WAIT_PARITY(sb + SM_MBAR, ph);
        ph ^= 1;
        asm volatile("tcgen05.fence::after_thread_sync;" ::: "memory");

        // ---- epi2: out = D2 + bo ----
        {
            const bool valid = (m0 + r) < M;
            float* op = out + (size_t)(m0 + r) * DF;
#pragma unroll
            for (int p = 0; p < 4; p++) {
                uint32_t dreg[32];
                LDTM_X32(dreg, D2 + p * 32);
                TM_WAIT_LD();
                if (valid) {
#pragma unroll
                    for (int j = 0; j < 8; j++) {
                        float4 v;
                        v.x = __uint_as_float(dreg[4 * j + 0]) + bos[p * 32 + 4 * j + 0];
                        v.y = __uint_as_float(dreg[4 * j + 1]) + bos[p * 32 + 4 * j + 1];
                        v.z = __uint_as_float(dreg[4 * j + 2]) + bos[p * 32 + 4 * j + 2];
                        v.w = __uint_as_float(dreg[4 * j + 3]) + bos[p * 32 + 4 * j + 3];
                        *(float4*)(op + p * 32 + 4 * j) = v;
                    }
                }
            }
        }
        asm volatile("tcgen05.fence::before_thread_sync;" ::: "memory");
        __syncthreads();
    }

    __syncthreads();
    if (wid == 0) {
        asm volatile("tcgen05.relinquish_alloc_permit.cta_group::1.sync.aligned;");
        asm volatile("tcgen05.dealloc.cta_group::1.sync.aligned.b32 %0, %1;"
                     :: "r"(tmem), "r"(256u));
    }

#else  // ------------------- FFMA fallback (plain sm_103 pass) -------------------

    float* As  = (float*)(smem + SMF_AS);   // [64][132]
    float* Hs  = (float*)(smem + SMF_HS);   // [64][132]
    float* W1s = (float*)(smem + SMF_W1);   // [128][128]
    float* W2s = (float*)(smem + SMF_W2);   // [128][128]
    float* bhs = (float*)(smem + SMF_BH);
    float* bos = (float*)(smem + SMF_BO);

    bhs[tid] = bh[tid];
    bos[tid] = bo[tid];
    {
        const float4* g1 = (const float4*)Wh;
        const float4* g2 = (const float4*)Wo;
        float4* s1 = (float4*)W1s;
        float4* s2 = (float4*)W2s;
#pragma unroll
        for (int i = 0; i < 32; i++) {
            s1[tid + i * 128] = g1[tid + i * 128];
            s2[tid + i * 128] = g2[tid + i * 128];
        }
    }
    __syncthreads();

    const int nTiles = (M + 63) >> 6;
    const int r = tid >> 1;        // row within 64-row tile
    const int h = tid & 1;         // column half: h*64 .. h*64+63

    for (int t = blockIdx.x; t < nTiles; t += gridDim.x) {
        const int m0 = t << 6;

        // load A tile [64][128] (warp-per-row pattern: warp handles rows wid,wid+4,...)
        for (int rr = wid; rr < 64; rr += 4) {
            const int row = m0 + rr;
            float4 v = make_float4(0.f, 0.f, 0.f, 0.f);
            if (row < M) v = *(const float4*)(A + (size_t)row * DF + lid * 4);
            *(float4*)(&As[rr * 132 + lid * 4]) = v;
        }
        __syncthreads();

        // GEMM1 + relu -> Hs. Each thread: row r, cols h*64..h*64+63 (2 blocks of 32)
#pragma unroll
        for (int nb = 0; nb < 2; nb++) {
            const int c0 = h * 64 + nb * 32;
            float acc[32];
#pragma unroll
            for (int j = 0; j < 32; j++) acc[j] = bhs[c0 + j];
#pragma unroll 4
            for (int k = 0; k < 128; k++) {
                float a = As[r * 132 + k];
                const float4* wrow = (const float4*)(&W1s[k * 128 + c0]);
#pragma unroll
                for (int j4 = 0; j4 < 8; j4++) {
                    float4 b = wrow[j4];
                    acc[j4 * 4 + 0] = fmaf(a, b.x, acc[j4 * 4 + 0]);
                    acc[j4 * 4 + 1] = fmaf(a, b.y, acc[j4 * 4 + 1]);
                    acc[j4 * 4 + 2] = fmaf(a, b.z, acc[j4 * 4 + 2]);
                    acc[j4 * 4 + 3] = fmaf(a, b.w, acc[j4 * 4 + 3]);
                }
            }
#pragma unroll
            for (int j = 0; j < 32; j++) Hs[r * 132 + c0 + j] = fmaxf(acc[j], 0.f);
        }
        __syncthreads();

        // GEMM2 -> out
        const bool valid = (m0 + r) < M;
#pragma unroll
        for (int nb = 0; nb < 2; nb++) {
            const int c0 = h * 64 + nb * 32;
            float acc[32];
#pragma unroll
            for (int j = 0; j < 32; j++) acc[j] = bos[c0 + j];
#pragma unroll 4
            for (int k = 0; k < 128; k++) {
                float a = Hs[r * 132 + k];
                const float4* wrow = (const float4*)(&W2s[k * 128 + c0]);
#pragma unroll
                for (int j4 = 0; j4 < 8; j4++) {
                    float4 b = wrow[j4];
                    acc[j4 * 4 + 0] = fmaf(a, b.x, acc[j4 * 4 + 0]);
                    acc[j4 * 4 + 1] = fmaf(a, b.y, acc[j4 * 4 + 1]);
                    acc[j4 * 4 + 2] = fmaf(a, b.z, acc[j4 * 4 + 2]);
                    acc[j4 * 4 + 3] = fmaf(a, b.w, acc[j4 * 4 + 3]);
                }
            }
            if (valid) {
                float* op = out + (size_t)(m0 + r) * DF + c0;
#pragma unroll
                for (int j4 = 0; j4 < 8; j4++)
                    *(float4*)(op + j4 * 4) =
                        make_float4(acc[j4 * 4], acc[j4 * 4 + 1], acc[j4 * 4 + 2], acc[j4 * 4 + 3]);
            }
        }
        __syncthreads();
    }
#endif
}

// ---------------------------------------------------------------------------
// agg = X (vectorized copy)
// ---------------------------------------------------------------------------
__global__ void copy_init_kernel(const float4* __restrict__ src,
                                 float4* __restrict__ dst, int n4) {
    int i = blockIdx.x * blockDim.x + threadIdx.x;
    if (i < n4) dst[i] = src[i];
}

// ---------------------------------------------------------------------------
// Edge scatter: red.global.add.v4.f32, one warp per edge (both directions)
// ---------------------------------------------------------------------------
__global__ void edge_scatter_kernel(const float* __restrict__ X,
                                    const int* __restrict__ ra,
                                    const int* __restrict__ rb,
                                    float* __restrict__ agg, int nE) {
    int e = blockIdx.x * (blockDim.x >> 5) + (threadIdx.x >> 5);
    if (e >= nE) return;
    int lane = threadIdx.x & 31;
    int a = ra[e];
    int b = rb[e];
    const float4 xb = *reinterpret_cast<const float4*>(X + (size_t)b * DF + lane * 4);
    const float4 xa = *reinterpret_cast<const float4*>(X + (size_t)a * DF + lane * 4);
    float* pa = agg + (size_t)a * DF + lane * 4;
    float* pb = agg + (size_t)b * DF + lane * 4;
    asm volatile("red.global.add.v4.f32 [%0], {%1, %2, %3, %4};"
                 :: "l"(pa), "f"(xb.x), "f"(xb.y), "f"(xb.z), "f"(xb.w) : "memory");
    asm volatile("red.global.add.v4.f32 [%0], {%1, %2, %3, %4};"
                 :: "l"(pb), "f"(xa.x), "f"(xa.y), "f"(xa.z), "f"(xa.w) : "memory");
}

// ---------------------------------------------------------------------------
// Launch. Inputs: X, ref_a, ref_b, W_hidden, b_hidden, W_out, b_out
// ---------------------------------------------------------------------------
extern "C" void kernel_launch(void* const* d_in, const int* in_sizes, int n_in,
                              void* d_out, int out_size) {
    const float* X  = (const float*)d_in[0];
    const int*   ra = (const int*)  d_in[1];
    const int*   rb = (const int*)  d_in[2];
    const float* Wh = (const float*)d_in[3];
    const float* bh = (const float*)d_in[4];
    const float* Wo = (const float*)d_in[5];
    const float* bo = (const float*)d_in[6];
    float* out = (float*)d_out;

    const int M  = in_sizes[0] / DF;
    const int nE = in_sizes[1];

    float* agg = nullptr;
    cudaGetSymbolAddress((void**)&agg, g_agg);

    cudaFuncSetAttribute(fused_mlp_kernel,
                         cudaFuncAttributeMaxDynamicSharedMemorySize, SM_TOTAL);

    // 1) agg = X
    {
        int n4 = M * DF / 4;
        copy_init_kernel<<<(n4 + 255) / 256, 256>>>((const float4*)X, (float4*)agg, n4);
    }
    // 2) scatter-add both edge directions
    {
        int wpb = 8;
        edge_scatter_kernel<<<(nE + wpb - 1) / wpb, wpb * 32>>>(X, ra, rb, agg, nE);
    }
    // 3+4) fused persistent MLP
    fused_mlp_kernel<<<148, 128, SM_TOTAL>>>(agg, Wh, bh, Wo, bo, out, M);
}